// round 7
// baseline (speedup 1.0000x reference)
#include <cuda_runtime.h>

#define B_   8
#define N_   16384
#define NC_  64
#define C_   256
#define TP_  128
#define SPD_STRIDE 72    // dup-P stage row stride (floats); 72%32=8 -> conflict-free reads
#define SED_STRIDE 136   // dup-E stage row stride; 136%32=8 -> conflict-free reads

// Scratch (device globals — no allocation allowed)
__device__ float g_M[B_ * C_ * NC_];  // [b][c][k]
__device__ float g_t[B_ * NC_];       // [b][k]

typedef unsigned long long ull;

__device__ __forceinline__ ull pack2(float x, float y) {
    ull r; asm("mov.b64 %0, {%1, %2};" : "=l"(r) : "f"(x), "f"(y)); return r;
}
__device__ __forceinline__ void unpack2(ull v, float &x, float &y) {
    asm("mov.b64 {%0, %1}, %2;" : "=f"(x), "=f"(y) : "l"(v));
}
__device__ __forceinline__ void fma2(ull &acc, ull a, ull b) {
    asm("fma.rn.f32x2 %0, %1, %2, %3;" : "=l"(acc) : "l"(a), "l"(b), "l"(acc));
}
__device__ __forceinline__ float warp_sum(float s) {
#pragma unroll
    for (int off = 16; off; off >>= 1) s += __shfl_xor_sync(0xffffffffu, s, off);
    return s;
}

// ---------------------------------------------------------------------------
// Prep kernel. grid 64 = (b<<3 | kt), block 256. 8 centroids per block.
//  A: cproj[k,d] = sum_e Ctr[b,k,e]*Wc[e,d] + bc[d]  (thread=d, Wc tiled via smem)
//     t[b,k]     = sum_d bp[d]*cproj[k,d]
//  B: M[b,c,k]   = sum_d Wp[c,d]*cproj[k,d]          (thread=c, Wp tiled via smem)
// ---------------------------------------------------------------------------
__global__ void prep_kernel(const float* __restrict__ cf, const float* __restrict__ Wp,
                            const float* __restrict__ Wc, const float* __restrict__ bp,
                            const float* __restrict__ bc) {
    __shared__ __align__(16) float sCt[C_ * 8];    // Ctr^T [e][k]
    __shared__ __align__(16) float sCPt[C_ * 8];   // cproj^T [d][k]
    __shared__ __align__(16) float sTile[8448];    // W tile (A: [ee][d] s264 / B: [c][dd] s33)
    __shared__ float sPart[8][8];

    int b  = blockIdx.x >> 3;
    int kt = blockIdx.x & 7;
    int tid = threadIdx.x, w = tid >> 5, l = tid & 31;

    // Ctr^T load (coalesced gmem)
#pragma unroll
    for (int i = 0; i < 8; i++)
        sCt[tid * 8 + i] = cf[(size_t)(b * NC_ + kt * 8 + i) * C_ + tid];
    __syncthreads();

    // ---- phase A ----
    int d = tid;
    float acc[8];
    {
        float bcv = bc[d];
#pragma unroll
        for (int j = 0; j < 8; j++) acc[j] = bcv;
    }
    const float4* Wc4 = (const float4*)Wc;
    for (int e0 = 0; e0 < C_; e0 += 32) {
#pragma unroll
        for (int i = 0; i < 8; i++) {
            int q = tid + 256 * i;
            int ee = q >> 6, jf = q & 63;
            ((float4*)sTile)[ee * 66 + jf] = Wc4[(size_t)(e0 + ee) * 64 + jf];
        }
        __syncthreads();
#pragma unroll 4
        for (int ee = 0; ee < 32; ee++) {
            float wv = sTile[ee * 264 + d];
            float4 c0 = *(const float4*)(sCt + (e0 + ee) * 8);
            float4 c1 = *(const float4*)(sCt + (e0 + ee) * 8 + 4);
            acc[0] += wv*c0.x; acc[1] += wv*c0.y; acc[2] += wv*c0.z; acc[3] += wv*c0.w;
            acc[4] += wv*c1.x; acc[5] += wv*c1.y; acc[6] += wv*c1.z; acc[7] += wv*c1.w;
        }
        __syncthreads();
    }
    // t partials
    {
        float m = bp[d];
#pragma unroll
        for (int j = 0; j < 8; j++) {
            float s = warp_sum(acc[j] * m);
            if (l == 0) sPart[w][j] = s;
        }
    }
    *(float4*)(sCPt + d * 8)     = make_float4(acc[0], acc[1], acc[2], acc[3]);
    *(float4*)(sCPt + d * 8 + 4) = make_float4(acc[4], acc[5], acc[6], acc[7]);
    __syncthreads();
    if (tid < 8) {
        float s = 0.f;
#pragma unroll
        for (int ww = 0; ww < 8; ww++) s += sPart[ww][tid];
        g_t[b * NC_ + kt * 8 + tid] = s;
    }

    // ---- phase B ----
    int c = tid;
    float a2[8] = {0.f,0.f,0.f,0.f,0.f,0.f,0.f,0.f};
    const float4* Wp4 = (const float4*)Wp;
    for (int d0 = 0; d0 < C_; d0 += 32) {
        __syncthreads();   // protect sTile from prior reads
#pragma unroll
        for (int i = 0; i < 8; i++) {
            int q = tid + 256 * i;
            int cc = q >> 3, jf = q & 7;
            float4 v = Wp4[(size_t)cc * 64 + d0 / 4 + jf];
            float* dst = sTile + cc * 33 + jf * 4;      // stride 33: conflict-free reads
            dst[0] = v.x; dst[1] = v.y; dst[2] = v.z; dst[3] = v.w;
        }
        __syncthreads();
#pragma unroll 4
        for (int dd = 0; dd < 32; dd++) {
            float wv = sTile[c * 33 + dd];
            float4 q0 = *(const float4*)(sCPt + (d0 + dd) * 8);
            float4 q1 = *(const float4*)(sCPt + (d0 + dd) * 8 + 4);
            a2[0] += wv*q0.x; a2[1] += wv*q0.y; a2[2] += wv*q0.z; a2[3] += wv*q0.w;
            a2[4] += wv*q1.x; a2[5] += wv*q1.y; a2[6] += wv*q1.z; a2[7] += wv*q1.w;
        }
    }
#pragma unroll
    for (int j = 0; j < 8; j++)
        g_M[(size_t)(b * C_ + c) * NC_ + kt * 8 + j] = a2[j];
}

// ---------------------------------------------------------------------------
// Main kernel. Block 256 thr, 128 points. Tile: 4 pts (pt_g+32p) x 8 k/ch (kg).
// Operands pre-DUPLICATED in smem -> fma.rn.f32x2 scalar sides load as pairs,
// no pack MOVs in hot loops.
// smem overlay (25600 floats = 100 KB):
//   phase 1: sM [0,16384) M[c][64];  sPd [16384, 16384+128*72)
//   phase 2: sE [0, 128*136);        sCtr [17408, 17408+4096)
// ---------------------------------------------------------------------------
__global__ __launch_bounds__(256, 2)
void attn_main_kernel(const float* __restrict__ pf, const float* __restrict__ cf,
                      float* __restrict__ out) {
    extern __shared__ __align__(16) float sm[];
    float* sM   = sm;
    float* sPd  = sm + 16384;
    float* sE   = sm;
    float* sCtr = sm + 17408;
    __shared__ __align__(16) float st[NC_];

    int b    = blockIdx.x >> 7;
    int tile = blockIdx.x & 127;
    int tid  = threadIdx.x;
    int pt_g = tid >> 3;
    int kg   = tid & 7;

    {
        const float4* Ms = (const float4*)(g_M + (size_t)b * C_ * NC_);
        float4* s4 = (float4*)sM;
#pragma unroll
        for (int i = 0; i < 16; i++) s4[tid + 256 * i] = Ms[tid + 256 * i];
        if (tid < NC_) st[tid] = g_t[b * NC_ + tid];
    }
    __syncthreads();

    size_t ptbase = (size_t)b * N_ + (size_t)tile * TP_;
    const float* pbase = pf + ptbase * C_;
    float* obase = out + ptbase * C_;

    // ---- phase 1: scores ----
    ull acc[4][4];
    {
        const ull* t2 = (const ull*)st;
        ull i0 = t2[2*kg], i1 = t2[2*kg+1], i2 = t2[16+2*kg], i3 = t2[17+2*kg];
#pragma unroll
        for (int p = 0; p < 4; p++) {
            acc[p][0] = i0; acc[p][1] = i1; acc[p][2] = i2; acc[p][3] = i3;
        }
    }

#pragma unroll 1
    for (int cc = 0; cc < 8; cc++) {
        if (cc) __syncthreads();
        // stage P chunk, duplicated: (x,x,y,y,z,z,w,w)
#pragma unroll
        for (int i = 0; i < 4; i++) {
            int q  = tid + 256 * i;
            int pt = q >> 3, jf = q & 7;
            float4 v = *(const float4*)(pbase + (size_t)pt * C_ + cc * 32 + jf * 4);
            float4* dst = (float4*)(sPd + pt * SPD_STRIDE + jf * 8);
            dst[0] = make_float4(v.x, v.x, v.y, v.y);
            dst[1] = make_float4(v.z, v.z, v.w, v.w);
        }
        __syncthreads();

#pragma unroll 2
        for (int c4 = 0; c4 < 8; c4++) {
            ull pp[4][4];
#pragma unroll
            for (int p = 0; p < 4; p++) {
                const ulonglong2* pr =
                    (const ulonglong2*)(sPd + (pt_g + 32 * p) * SPD_STRIDE + c4 * 8);
                ulonglong2 a = pr[0], bq = pr[1];
                pp[p][0] = a.x; pp[p][1] = a.y; pp[p][2] = bq.x; pp[p][3] = bq.y;
            }
#pragma unroll
            for (int j = 0; j < 4; j++) {
                const float* mrow = sM + (size_t)(cc * 32 + c4 * 4 + j) * NC_;
                ulonglong2 m0 = *(const ulonglong2*)(mrow + kg * 4);
                ulonglong2 m1 = *(const ulonglong2*)(mrow + 32 + kg * 4);
#pragma unroll
                for (int p = 0; p < 4; p++) {
                    fma2(acc[p][0], m0.x, pp[p][j]);
                    fma2(acc[p][1], m0.y, pp[p][j]);
                    fma2(acc[p][2], m1.x, pp[p][j]);
                    fma2(acc[p][3], m1.y, pp[p][j]);
                }
            }
        }
    }

    // ---- softmax per point (8 kg lanes hold the 64 k) ----
#pragma unroll
    for (int p = 0; p < 4; p++) {
        float x0,x1,x2,x3,x4,x5,x6,x7;
        unpack2(acc[p][0], x0, x1); unpack2(acc[p][1], x2, x3);
        unpack2(acc[p][2], x4, x5); unpack2(acc[p][3], x6, x7);
        float mx = fmaxf(fmaxf(fmaxf(x0,x1),fmaxf(x2,x3)), fmaxf(fmaxf(x4,x5),fmaxf(x6,x7)));
#pragma unroll
        for (int off = 1; off < 8; off <<= 1)
            mx = fmaxf(mx, __shfl_xor_sync(0xffffffffu, mx, off));
        x0 = __expf(x0-mx); x1 = __expf(x1-mx); x2 = __expf(x2-mx); x3 = __expf(x3-mx);
        x4 = __expf(x4-mx); x5 = __expf(x5-mx); x6 = __expf(x6-mx); x7 = __expf(x7-mx);
        float s = ((x0+x1)+(x2+x3)) + ((x4+x5)+(x6+x7));
#pragma unroll
        for (int off = 1; off < 8; off <<= 1)
            s += __shfl_xor_sync(0xffffffffu, s, off);
        float inv = 1.0f / s;
        acc[p][0] = pack2(x0*inv, x1*inv); acc[p][1] = pack2(x2*inv, x3*inv);
        acc[p][2] = pack2(x4*inv, x5*inv); acc[p][3] = pack2(x6*inv, x7*inv);
    }

    __syncthreads();   // all phase-1 smem reads complete (sE overlays sM)

    // ---- stage E duplicated: sE[pt][2k] ----
#pragma unroll
    for (int p = 0; p < 4; p++) {
        float* er = sE + (pt_g + 32 * p) * SED_STRIDE;
        float x0,x1,x2,x3;
        unpack2(acc[p][0], x0, x1); unpack2(acc[p][1], x2, x3);
        ((float4*)(er + kg * 8))[0] = make_float4(x0, x0, x1, x1);
        ((float4*)(er + kg * 8))[1] = make_float4(x2, x2, x3, x3);
        unpack2(acc[p][2], x0, x1); unpack2(acc[p][3], x2, x3);
        ((float4*)(er + 64 + kg * 8))[0] = make_float4(x0, x0, x1, x1);
        ((float4*)(er + 64 + kg * 8))[1] = make_float4(x2, x2, x3, x3);
    }

    // ---- phase 2: stream Ctr 64-ch chunks ----
#pragma unroll 1
    for (int cc2 = 0; cc2 < 4; cc2++) {
        if (cc2) __syncthreads();
#pragma unroll
        for (int i = 0; i < 4; i++) {
            int q = tid + 256 * i;
            int k = q >> 4, jf = q & 15;
            *(float4*)(sCtr + k * 64 + jf * 4) =
                *(const float4*)(cf + (size_t)(b * NC_ + k) * C_ + cc2 * 64 + jf * 4);
        }
        __syncthreads();

        ull a2[4][4];
#pragma unroll
        for (int p = 0; p < 4; p++) { a2[p][0]=0; a2[p][1]=0; a2[p][2]=0; a2[p][3]=0; }

#pragma unroll 2
        for (int k4 = 0; k4 < 16; k4++) {
            ull ee[4][4];
#pragma unroll
            for (int p = 0; p < 4; p++) {
                const ulonglong2* er =
                    (const ulonglong2*)(sE + (pt_g + 32 * p) * SED_STRIDE + k4 * 8);
                ulonglong2 a = er[0], bq = er[1];
                ee[p][0] = a.x; ee[p][1] = a.y; ee[p][2] = bq.x; ee[p][3] = bq.y;
            }
#pragma unroll
            for (int j = 0; j < 4; j++) {
                const float* crow = sCtr + (size_t)(k4 * 4 + j) * 64;
                ulonglong2 c0 = *(const ulonglong2*)(crow + kg * 4);
                ulonglong2 c1 = *(const ulonglong2*)(crow + 32 + kg * 4);
#pragma unroll
                for (int p = 0; p < 4; p++) {
                    fma2(a2[p][0], c0.x, ee[p][j]);
                    fma2(a2[p][1], c0.y, ee[p][j]);
                    fma2(a2[p][2], c1.x, ee[p][j]);
                    fma2(a2[p][3], c1.y, ee[p][j]);
                }
            }
        }

        // epilogue: residual + coalesced store
#pragma unroll
        for (int p = 0; p < 4; p++) {
            size_t roff = (size_t)(pt_g + 32 * p) * C_ + cc2 * 64 + kg * 4;
            float4 v0 = *(const float4*)(pbase + roff);
            float4 v1 = *(const float4*)(pbase + roff + 32);
            float a, bb;
            unpack2(a2[p][0], a, bb); v0.x += a; v0.y += bb;
            unpack2(a2[p][1], a, bb); v0.z += a; v0.w += bb;
            unpack2(a2[p][2], a, bb); v1.x += a; v1.y += bb;
            unpack2(a2[p][3], a, bb); v1.z += a; v1.w += bb;
            *(float4*)(obase + roff)      = v0;
            *(float4*)(obase + roff + 32) = v1;
        }
    }
}

// ---------------------------------------------------------------------------
extern "C" void kernel_launch(void* const* d_in, const int* in_sizes, int n_in,
                              void* d_out, int out_size) {
    const float* pf = (const float*)d_in[0];   // point_features   (B,N,C)
    const float* cf = (const float*)d_in[1];   // centroid_features(B,NC,C)
    const float* Wp = (const float*)d_in[2];   // (C,C)
    const float* bp = (const float*)d_in[3];   // (C,)
    const float* Wc = (const float*)d_in[4];   // (C,C)
    const float* bc = (const float*)d_in[5];   // (C,)
    float* out = (float*)d_out;

    const int smem_bytes = 25600 * sizeof(float);   // 100 KB

    static bool attr_set = false;
    if (!attr_set) {
        cudaFuncSetAttribute(attn_main_kernel,
                             cudaFuncAttributeMaxDynamicSharedMemorySize,
                             smem_bytes);
        attr_set = true;
    }

    prep_kernel<<<B_ * 8, 256>>>(cf, Wp, Wc, bp, bc);
    attn_main_kernel<<<B_ * (N_ / TP_), 256, smem_bytes>>>(pf, cf, out);
}

// round 8
// speedup vs baseline: 1.0550x; 1.0550x over previous
#include <cuda_runtime.h>

#define B_   8
#define N_   16384
#define NC_  64
#define C_   256
#define TP_  256
#define SP_STRIDE 36     // P stage row stride; addr/16 = pt_g*9+c4 -> conflict-free
#define SE_STRIDE 68     // E stage row stride; addr/16 = pt_g*17+k4 -> conflict-free

// Scratch (device globals — no allocation allowed)
__device__ float g_M[B_ * C_ * NC_];  // [b][c][k]
__device__ float g_t[B_ * NC_];       // [b][k]

typedef unsigned long long ull;

__device__ __forceinline__ ull pack2(float x, float y) {
    ull r; asm("mov.b64 %0, {%1, %2};" : "=l"(r) : "f"(x), "f"(y)); return r;
}
__device__ __forceinline__ void unpack2(ull v, float &x, float &y) {
    asm("mov.b64 {%0, %1}, %2;" : "=f"(x), "=f"(y) : "l"(v));
}
__device__ __forceinline__ void fma2(ull &acc, ull a, ull b) {
    asm("fma.rn.f32x2 %0, %1, %2, %3;" : "=l"(acc) : "l"(a), "l"(b), "l"(acc));
}
__device__ __forceinline__ float warp_sum(float s) {
#pragma unroll
    for (int off = 16; off; off >>= 1) s += __shfl_xor_sync(0xffffffffu, s, off);
    return s;
}

// ---------------------------------------------------------------------------
// Prep kernel. grid 128 = (b<<4 | kt), block 256. 4 centroids per block.
//  A: cproj[k,d] = sum_e Ctr[b,k,e]*Wc[e,d] + bc[d]  (thread=d, Wc smem tiles)
//     t[b,k]     = sum_d bp[d]*cproj[k,d]
//  B: M[b,c,k]   = sum_d Wp[c,d]*cproj[k,d]          (thread=c, Wp smem tiles)
// ---------------------------------------------------------------------------
__global__ void prep_kernel(const float* __restrict__ cf, const float* __restrict__ Wp,
                            const float* __restrict__ Wc, const float* __restrict__ bp,
                            const float* __restrict__ bc) {
    __shared__ __align__(16) float sCt[C_ * 4];    // Ctr^T [e][k] (4 k)
    __shared__ __align__(16) float sCPt[C_ * 4];   // cproj^T [d][k]
    __shared__ __align__(16) float sTile[8448];    // W tile
    __shared__ float sPart[8][4];

    int b  = blockIdx.x >> 4;
    int kt = blockIdx.x & 15;
    int tid = threadIdx.x, w = tid >> 5, l = tid & 31;

#pragma unroll
    for (int i = 0; i < 4; i++)
        sCt[tid * 4 + i] = cf[(size_t)(b * NC_ + kt * 4 + i) * C_ + tid];
    __syncthreads();

    // ---- phase A ----
    int d = tid;
    float acc[4];
    {
        float bcv = bc[d];
#pragma unroll
        for (int j = 0; j < 4; j++) acc[j] = bcv;
    }
    const float4* Wc4 = (const float4*)Wc;
    for (int e0 = 0; e0 < C_; e0 += 32) {
#pragma unroll
        for (int i = 0; i < 8; i++) {
            int q = tid + 256 * i;
            int ee = q >> 6, jf = q & 63;
            ((float4*)sTile)[ee * 66 + jf] = Wc4[(size_t)(e0 + ee) * 64 + jf];
        }
        __syncthreads();
#pragma unroll 4
        for (int ee = 0; ee < 32; ee++) {
            float wv = sTile[ee * 264 + d];
            float4 c0 = *(const float4*)(sCt + (e0 + ee) * 4);
            acc[0] += wv*c0.x; acc[1] += wv*c0.y; acc[2] += wv*c0.z; acc[3] += wv*c0.w;
        }
        __syncthreads();
    }
    {
        float m = bp[d];
#pragma unroll
        for (int j = 0; j < 4; j++) {
            float s = warp_sum(acc[j] * m);
            if (l == 0) sPart[w][j] = s;
        }
    }
    *(float4*)(sCPt + d * 4) = make_float4(acc[0], acc[1], acc[2], acc[3]);
    __syncthreads();
    if (tid < 4) {
        float s = 0.f;
#pragma unroll
        for (int ww = 0; ww < 8; ww++) s += sPart[ww][tid];
        g_t[b * NC_ + kt * 4 + tid] = s;
    }

    // ---- phase B ----
    int c = tid;
    float a2[4] = {0.f, 0.f, 0.f, 0.f};
    const float4* Wp4 = (const float4*)Wp;
    for (int d0 = 0; d0 < C_; d0 += 32) {
        __syncthreads();
#pragma unroll
        for (int i = 0; i < 8; i++) {
            int q = tid + 256 * i;
            int cc = q >> 3, jf = q & 7;
            float4 v = Wp4[(size_t)cc * 64 + d0 / 4 + jf];
            float* dst = sTile + cc * 33 + jf * 4;
            dst[0] = v.x; dst[1] = v.y; dst[2] = v.z; dst[3] = v.w;
        }
        __syncthreads();
#pragma unroll 4
        for (int dd = 0; dd < 32; dd++) {
            float wv = sTile[c * 33 + dd];
            float4 q0 = *(const float4*)(sCPt + (d0 + dd) * 4);
            a2[0] += wv*q0.x; a2[1] += wv*q0.y; a2[2] += wv*q0.z; a2[3] += wv*q0.w;
        }
    }
#pragma unroll
    for (int j = 0; j < 4; j++)
        g_M[(size_t)(b * C_ + c) * NC_ + kt * 4 + j] = a2[j];
}

// ---------------------------------------------------------------------------
// Main kernel. Block 256 thr, 256 points. Tile: 8 pts (pt_g+32*pp) x 8 k/ch (kg).
// Non-duplicated operand stages; scalar broadcast built with pack MOVs (ALU pipe).
// Per warp per c4: 8 M-LDS.128 + 8 P-LDS.128 per 128 FFMA2 -> L1 == FMA balanced.
// smem overlay (25600 floats = 100 KB):
//   phase 1: sM [0,16384) M[c][64];  sP [16384, 16384+256*36)
//   phase 2: sE [0, 256*68);         sCtr [17408, 17408+4096)
// ---------------------------------------------------------------------------
__global__ __launch_bounds__(256, 2)
void attn_main_kernel(const float* __restrict__ pf, const float* __restrict__ cf,
                      float* __restrict__ out) {
    extern __shared__ __align__(16) float sm[];
    float* sM   = sm;
    float* sP   = sm + 16384;
    float* sE   = sm;
    float* sCtr = sm + 17408;
    __shared__ __align__(16) float st[NC_];

    int b    = blockIdx.x >> 6;
    int tile = blockIdx.x & 63;
    int tid  = threadIdx.x;
    int pt_g = tid >> 3;   // 0..31
    int kg   = tid & 7;

    {
        const float4* Ms = (const float4*)(g_M + (size_t)b * C_ * NC_);
        float4* s4 = (float4*)sM;
#pragma unroll
        for (int i = 0; i < 16; i++) s4[tid + 256 * i] = Ms[tid + 256 * i];
        if (tid < NC_) st[tid] = g_t[b * NC_ + tid];
    }
    __syncthreads();

    size_t ptbase = (size_t)b * N_ + (size_t)tile * TP_;
    const float* pbase = pf + ptbase * C_;
    float* obase = out + ptbase * C_;

    // ---- phase 1: scores ----
    ull acc[8][4];
    {
        const ull* t2 = (const ull*)st;
        ull i0 = t2[2*kg], i1 = t2[2*kg+1], i2 = t2[16+2*kg], i3 = t2[17+2*kg];
#pragma unroll
        for (int p = 0; p < 8; p++) {
            acc[p][0] = i0; acc[p][1] = i1; acc[p][2] = i2; acc[p][3] = i3;
        }
    }

#pragma unroll 1
    for (int cc = 0; cc < 8; cc++) {
        if (cc) __syncthreads();
        // stage P[256 pts][32 ch] non-duplicated
#pragma unroll
        for (int i = 0; i < 8; i++) {
            int q  = tid + 256 * i;
            int pt = q >> 3, jf = q & 7;
            *(float4*)(sP + pt * SP_STRIDE + jf * 4) =
                *(const float4*)(pbase + (size_t)pt * C_ + cc * 32 + jf * 4);
        }
        __syncthreads();

#pragma unroll 2
        for (int c4 = 0; c4 < 8; c4++) {
            ulonglong2 m0[4], m1[4];
#pragma unroll
            for (int j = 0; j < 4; j++) {
                const float* mrow = sM + (size_t)(cc * 32 + c4 * 4 + j) * NC_;
                m0[j] = *(const ulonglong2*)(mrow + kg * 4);
                m1[j] = *(const ulonglong2*)(mrow + 32 + kg * 4);
            }
#pragma unroll
            for (int p = 0; p < 8; p++) {
                float4 pv = *(const float4*)(sP + (pt_g + 32 * p) * SP_STRIDE + c4 * 4);
                ull px = pack2(pv.x, pv.x);
                fma2(acc[p][0], m0[0].x, px); fma2(acc[p][1], m0[0].y, px);
                fma2(acc[p][2], m1[0].x, px); fma2(acc[p][3], m1[0].y, px);
                ull py = pack2(pv.y, pv.y);
                fma2(acc[p][0], m0[1].x, py); fma2(acc[p][1], m0[1].y, py);
                fma2(acc[p][2], m1[1].x, py); fma2(acc[p][3], m1[1].y, py);
                ull pz = pack2(pv.z, pv.z);
                fma2(acc[p][0], m0[2].x, pz); fma2(acc[p][1], m0[2].y, pz);
                fma2(acc[p][2], m1[2].x, pz); fma2(acc[p][3], m1[2].y, pz);
                ull pw = pack2(pv.w, pv.w);
                fma2(acc[p][0], m0[3].x, pw); fma2(acc[p][1], m0[3].y, pw);
                fma2(acc[p][2], m1[3].x, pw); fma2(acc[p][3], m1[3].y, pw);
            }
        }
    }

    // ---- softmax per point (8 kg lanes hold the 64 k) ----
#pragma unroll
    for (int p = 0; p < 8; p++) {
        float x0,x1,x2,x3,x4,x5,x6,x7;
        unpack2(acc[p][0], x0, x1); unpack2(acc[p][1], x2, x3);
        unpack2(acc[p][2], x4, x5); unpack2(acc[p][3], x6, x7);
        float mx = fmaxf(fmaxf(fmaxf(x0,x1),fmaxf(x2,x3)), fmaxf(fmaxf(x4,x5),fmaxf(x6,x7)));
#pragma unroll
        for (int off = 1; off < 8; off <<= 1)
            mx = fmaxf(mx, __shfl_xor_sync(0xffffffffu, mx, off));
        x0 = __expf(x0-mx); x1 = __expf(x1-mx); x2 = __expf(x2-mx); x3 = __expf(x3-mx);
        x4 = __expf(x4-mx); x5 = __expf(x5-mx); x6 = __expf(x6-mx); x7 = __expf(x7-mx);
        float s = ((x0+x1)+(x2+x3)) + ((x4+x5)+(x6+x7));
#pragma unroll
        for (int off = 1; off < 8; off <<= 1)
            s += __shfl_xor_sync(0xffffffffu, s, off);
        float inv = 1.0f / s;
        acc[p][0] = pack2(x0*inv, x1*inv); acc[p][1] = pack2(x2*inv, x3*inv);
        acc[p][2] = pack2(x4*inv, x5*inv); acc[p][3] = pack2(x6*inv, x7*inv);
    }

    __syncthreads();   // all phase-1 smem reads complete (sE overlays sM/sP)

    // ---- stage E non-duplicated: sE[pt][64] ----
#pragma unroll
    for (int p = 0; p < 8; p++) {
        float* er = sE + (pt_g + 32 * p) * SE_STRIDE;
        ulonglong2 e0; e0.x = acc[p][0]; e0.y = acc[p][1];
        ulonglong2 e1; e1.x = acc[p][2]; e1.y = acc[p][3];
        *(ulonglong2*)(er + kg * 4)      = e0;
        *(ulonglong2*)(er + 32 + kg * 4) = e1;
    }

    // ---- phase 2: stream Ctr 64-ch chunks ----
#pragma unroll 1
    for (int cc2 = 0; cc2 < 4; cc2++) {
        if (cc2) __syncthreads();
#pragma unroll
        for (int i = 0; i < 4; i++) {
            int q = tid + 256 * i;
            int k = q >> 4, jf = q & 15;
            *(float4*)(sCtr + k * 64 + jf * 4) =
                *(const float4*)(cf + (size_t)(b * NC_ + k) * C_ + cc2 * 64 + jf * 4);
        }
        __syncthreads();   // also makes sE visible on first pass

        ull a2[8][4];
#pragma unroll
        for (int p = 0; p < 8; p++) { a2[p][0]=0; a2[p][1]=0; a2[p][2]=0; a2[p][3]=0; }

#pragma unroll 2
        for (int k4 = 0; k4 < 16; k4++) {
            ulonglong2 c0[4], c1[4];
#pragma unroll
            for (int j = 0; j < 4; j++) {
                const float* crow = sCtr + (size_t)(k4 * 4 + j) * 64;
                c0[j] = *(const ulonglong2*)(crow + kg * 4);
                c1[j] = *(const ulonglong2*)(crow + 32 + kg * 4);
            }
#pragma unroll
            for (int p = 0; p < 8; p++) {
                float4 ev = *(const float4*)(sE + (pt_g + 32 * p) * SE_STRIDE + k4 * 4);
                ull ex = pack2(ev.x, ev.x);
                fma2(a2[p][0], c0[0].x, ex); fma2(a2[p][1], c0[0].y, ex);
                fma2(a2[p][2], c1[0].x, ex); fma2(a2[p][3], c1[0].y, ex);
                ull ey = pack2(ev.y, ev.y);
                fma2(a2[p][0], c0[1].x, ey); fma2(a2[p][1], c0[1].y, ey);
                fma2(a2[p][2], c1[1].x, ey); fma2(a2[p][3], c1[1].y, ey);
                ull ez = pack2(ev.z, ev.z);
                fma2(a2[p][0], c0[2].x, ez); fma2(a2[p][1], c0[2].y, ez);
                fma2(a2[p][2], c1[2].x, ez); fma2(a2[p][3], c1[2].y, ez);
                ull ew = pack2(ev.w, ev.w);
                fma2(a2[p][0], c0[3].x, ew); fma2(a2[p][1], c0[3].y, ew);
                fma2(a2[p][2], c1[3].x, ew); fma2(a2[p][3], c1[3].y, ew);
            }
        }

        // epilogue: residual + coalesced store
#pragma unroll
        for (int p = 0; p < 8; p++) {
            size_t roff = (size_t)(pt_g + 32 * p) * C_ + cc2 * 64 + kg * 4;
            float4 v0 = *(const float4*)(pbase + roff);
            float4 v1 = *(const float4*)(pbase + roff + 32);
            float a, bb;
            unpack2(a2[p][0], a, bb); v0.x += a; v0.y += bb;
            unpack2(a2[p][1], a, bb); v0.z += a; v0.w += bb;
            unpack2(a2[p][2], a, bb); v1.x += a; v1.y += bb;
            unpack2(a2[p][3], a, bb); v1.z += a; v1.w += bb;
            *(float4*)(obase + roff)      = v0;
            *(float4*)(obase + roff + 32) = v1;
        }
    }
}

// ---------------------------------------------------------------------------
extern "C" void kernel_launch(void* const* d_in, const int* in_sizes, int n_in,
                              void* d_out, int out_size) {
    const float* pf = (const float*)d_in[0];   // point_features   (B,N,C)
    const float* cf = (const float*)d_in[1];   // centroid_features(B,NC,C)
    const float* Wp = (const float*)d_in[2];   // (C,C)
    const float* bp = (const float*)d_in[3];   // (C,)
    const float* Wc = (const float*)d_in[4];   // (C,C)
    const float* bc = (const float*)d_in[5];   // (C,)
    float* out = (float*)d_out;

    const int smem_bytes = 25600 * sizeof(float);   // 100 KB

    static bool attr_set = false;
    if (!attr_set) {
        cudaFuncSetAttribute(attn_main_kernel,
                             cudaFuncAttributeMaxDynamicSharedMemorySize,
                             smem_bytes);
        attr_set = true;
    }

    prep_kernel<<<B_ * 16, 256>>>(cf, Wp, Wc, bp, bc);
    attn_main_kernel<<<B_ * (N_ / TP_), 256, smem_bytes>>>(pf, cf, out);
}

// round 9
// speedup vs baseline: 1.1547x; 1.0945x over previous
#include <cuda_runtime.h>

#define B_   8
#define N_   16384
#define NC_  64
#define C_   256
#define TP_  128
#define SE_STRIDE 68     // E row stride; banks conflict-free for octet reads

// Scratch (device globals — no allocation allowed)
__device__ float g_M[B_ * C_ * NC_];  // [b][c][k]
__device__ float g_t[B_ * NC_];       // [b][k]

typedef unsigned long long ull;

__device__ __forceinline__ ull pack2(float x, float y) {
    ull r; asm("mov.b64 %0, {%1, %2};" : "=l"(r) : "f"(x), "f"(y)); return r;
}
__device__ __forceinline__ void unpack2(ull v, float &x, float &y) {
    asm("mov.b64 {%0, %1}, %2;" : "=f"(x), "=f"(y) : "l"(v));
}
__device__ __forceinline__ void fma2(ull &acc, ull a, ull b) {
    asm("fma.rn.f32x2 %0, %1, %2, %3;" : "=l"(acc) : "l"(a), "l"(b), "l"(acc));
}
__device__ __forceinline__ float warp_sum(float s) {
#pragma unroll
    for (int off = 16; off; off >>= 1) s += __shfl_xor_sync(0xffffffffu, s, off);
    return s;
}

// ---------------------------------------------------------------------------
// Prep kernel (unchanged from round 8). grid 128 = (b<<4 | kt), block 256.
// ---------------------------------------------------------------------------
__global__ void prep_kernel(const float* __restrict__ cf, const float* __restrict__ Wp,
                            const float* __restrict__ Wc, const float* __restrict__ bp,
                            const float* __restrict__ bc) {
    __shared__ __align__(16) float sCt[C_ * 4];
    __shared__ __align__(16) float sCPt[C_ * 4];
    __shared__ __align__(16) float sTile[8448];
    __shared__ float sPart[8][4];

    int b  = blockIdx.x >> 4;
    int kt = blockIdx.x & 15;
    int tid = threadIdx.x, w = tid >> 5, l = tid & 31;

#pragma unroll
    for (int i = 0; i < 4; i++)
        sCt[tid * 4 + i] = cf[(size_t)(b * NC_ + kt * 4 + i) * C_ + tid];
    __syncthreads();

    int d = tid;
    float acc[4];
    {
        float bcv = bc[d];
#pragma unroll
        for (int j = 0; j < 4; j++) acc[j] = bcv;
    }
    const float4* Wc4 = (const float4*)Wc;
    for (int e0 = 0; e0 < C_; e0 += 32) {
#pragma unroll
        for (int i = 0; i < 8; i++) {
            int q = tid + 256 * i;
            int ee = q >> 6, jf = q & 63;
            ((float4*)sTile)[ee * 66 + jf] = Wc4[(size_t)(e0 + ee) * 64 + jf];
        }
        __syncthreads();
#pragma unroll 4
        for (int ee = 0; ee < 32; ee++) {
            float wv = sTile[ee * 264 + d];
            float4 c0 = *(const float4*)(sCt + (e0 + ee) * 4);
            acc[0] += wv*c0.x; acc[1] += wv*c0.y; acc[2] += wv*c0.z; acc[3] += wv*c0.w;
        }
        __syncthreads();
    }
    {
        float m = bp[d];
#pragma unroll
        for (int j = 0; j < 4; j++) {
            float s = warp_sum(acc[j] * m);
            if (l == 0) sPart[w][j] = s;
        }
    }
    *(float4*)(sCPt + d * 4) = make_float4(acc[0], acc[1], acc[2], acc[3]);
    __syncthreads();
    if (tid < 4) {
        float s = 0.f;
#pragma unroll
        for (int ww = 0; ww < 8; ww++) s += sPart[ww][tid];
        g_t[b * NC_ + kt * 4 + tid] = s;
    }

    int c = tid;
    float a2[4] = {0.f, 0.f, 0.f, 0.f};
    const float4* Wp4 = (const float4*)Wp;
    for (int d0 = 0; d0 < C_; d0 += 32) {
        __syncthreads();
#pragma unroll
        for (int i = 0; i < 8; i++) {
            int q = tid + 256 * i;
            int cc = q >> 3, jf = q & 7;
            float4 v = Wp4[(size_t)cc * 64 + d0 / 4 + jf];
            float* dst = sTile + cc * 33 + jf * 4;
            dst[0] = v.x; dst[1] = v.y; dst[2] = v.z; dst[3] = v.w;
        }
        __syncthreads();
#pragma unroll 4
        for (int dd = 0; dd < 32; dd++) {
            float wv = sTile[c * 33 + dd];
            float4 q0 = *(const float4*)(sCPt + (d0 + dd) * 4);
            a2[0] += wv*q0.x; a2[1] += wv*q0.y; a2[2] += wv*q0.z; a2[3] += wv*q0.w;
        }
    }
#pragma unroll
    for (int j = 0; j < 4; j++)
        g_M[(size_t)(b * C_ + c) * NC_ + kt * 4 + j] = a2[j];
}

// ---------------------------------------------------------------------------
// Main kernel. Block 256 thr, 128 points, 3 blocks/SM (24 warps).
// Tile: 4 pts (pt_g+32p) x 8 k/ch (kg octet {kg*4..+3} U {32+kg*4..+3}).
// Phase 1: P read DIRECTLY from gmem (8-lane broadcast LDG.128); M in smem.
// Phase 2: E via smem (cross-lane), Ctr staged per 64-ch chunk.
// dyn smem = 16384 floats (64 KB): phase1 sM[0,16384);
//   phase2 overlay: sE[0, 128*68), sCtr[8704, 8704+4096)
// ---------------------------------------------------------------------------
__global__ __launch_bounds__(256, 3)
void attn_main_kernel(const float* __restrict__ pf, const float* __restrict__ cf,
                      float* __restrict__ out) {
    extern __shared__ __align__(16) float sm[];
    float* sM   = sm;
    float* sE   = sm;
    float* sCtr = sm + 8704;
    __shared__ __align__(16) float st[NC_];

    int b    = blockIdx.x >> 7;
    int tile = blockIdx.x & 127;
    int tid  = threadIdx.x;
    int pt_g = tid >> 3;   // 0..31
    int kg   = tid & 7;

    {
        const float4* Ms = (const float4*)(g_M + (size_t)b * C_ * NC_);
        float4* s4 = (float4*)sM;
#pragma unroll
        for (int i = 0; i < 16; i++) s4[tid + 256 * i] = Ms[tid + 256 * i];
        if (tid < NC_) st[tid] = g_t[b * NC_ + tid];
    }
    __syncthreads();

    size_t ptbase = (size_t)b * N_ + (size_t)tile * TP_;
    const float* pbase = pf + ptbase * C_;
    float* obase = out + ptbase * C_;

    const float* prow[4];
#pragma unroll
    for (int p = 0; p < 4; p++) prow[p] = pbase + (size_t)(pt_g + 32 * p) * C_;

    // ---- phase 1: scores (single sync, P direct from gmem) ----
    ull acc[4][4];
    {
        const ull* t2 = (const ull*)st;
        ull i0 = t2[2*kg], i1 = t2[2*kg+1], i2 = t2[16+2*kg], i3 = t2[17+2*kg];
#pragma unroll
        for (int p = 0; p < 4; p++) {
            acc[p][0] = i0; acc[p][1] = i1; acc[p][2] = i2; acc[p][3] = i3;
        }
    }

#pragma unroll 2
    for (int c4 = 0; c4 < 64; c4++) {
        float4 pv[4];
#pragma unroll
        for (int p = 0; p < 4; p++)
            pv[p] = *(const float4*)(prow[p] + c4 * 4);   // 8-lane broadcast LDG

        ulonglong2 m0[4], m1[4];
#pragma unroll
        for (int j = 0; j < 4; j++) {
            const float* mrow = sM + (size_t)(c4 * 4 + j) * NC_;
            m0[j] = *(const ulonglong2*)(mrow + kg * 4);
            m1[j] = *(const ulonglong2*)(mrow + 32 + kg * 4);
        }
#pragma unroll
        for (int p = 0; p < 4; p++) {
            ull px = pack2(pv[p].x, pv[p].x);
            fma2(acc[p][0], m0[0].x, px); fma2(acc[p][1], m0[0].y, px);
            fma2(acc[p][2], m1[0].x, px); fma2(acc[p][3], m1[0].y, px);
            ull py = pack2(pv[p].y, pv[p].y);
            fma2(acc[p][0], m0[1].x, py); fma2(acc[p][1], m0[1].y, py);
            fma2(acc[p][2], m1[1].x, py); fma2(acc[p][3], m1[1].y, py);
            ull pz = pack2(pv[p].z, pv[p].z);
            fma2(acc[p][0], m0[2].x, pz); fma2(acc[p][1], m0[2].y, pz);
            fma2(acc[p][2], m1[2].x, pz); fma2(acc[p][3], m1[2].y, pz);
            ull pw = pack2(pv[p].w, pv[p].w);
            fma2(acc[p][0], m0[3].x, pw); fma2(acc[p][1], m0[3].y, pw);
            fma2(acc[p][2], m1[3].x, pw); fma2(acc[p][3], m1[3].y, pw);
        }
    }

    // ---- softmax per point (8 kg lanes hold the 64 k) ----
#pragma unroll
    for (int p = 0; p < 4; p++) {
        float x0,x1,x2,x3,x4,x5,x6,x7;
        unpack2(acc[p][0], x0, x1); unpack2(acc[p][1], x2, x3);
        unpack2(acc[p][2], x4, x5); unpack2(acc[p][3], x6, x7);
        float mx = fmaxf(fmaxf(fmaxf(x0,x1),fmaxf(x2,x3)), fmaxf(fmaxf(x4,x5),fmaxf(x6,x7)));
#pragma unroll
        for (int off = 1; off < 8; off <<= 1)
            mx = fmaxf(mx, __shfl_xor_sync(0xffffffffu, mx, off));
        x0 = __expf(x0-mx); x1 = __expf(x1-mx); x2 = __expf(x2-mx); x3 = __expf(x3-mx);
        x4 = __expf(x4-mx); x5 = __expf(x5-mx); x6 = __expf(x6-mx); x7 = __expf(x7-mx);
        float s = ((x0+x1)+(x2+x3)) + ((x4+x5)+(x6+x7));
#pragma unroll
        for (int off = 1; off < 8; off <<= 1)
            s += __shfl_xor_sync(0xffffffffu, s, off);
        float inv = 1.0f / s;
        acc[p][0] = pack2(x0*inv, x1*inv); acc[p][1] = pack2(x2*inv, x3*inv);
        acc[p][2] = pack2(x4*inv, x5*inv); acc[p][3] = pack2(x6*inv, x7*inv);
    }

    __syncthreads();   // all phase-1 sM reads complete (sE/sCtr overlay sM)

    // ---- stage E: sE[pt][64] ----
#pragma unroll
    for (int p = 0; p < 4; p++) {
        float* er = sE + (pt_g + 32 * p) * SE_STRIDE;
        ulonglong2 e0; e0.x = acc[p][0]; e0.y = acc[p][1];
        ulonglong2 e1; e1.x = acc[p][2]; e1.y = acc[p][3];
        *(ulonglong2*)(er + kg * 4)      = e0;
        *(ulonglong2*)(er + 32 + kg * 4) = e1;
    }

    // ---- phase 2: stream Ctr 64-ch chunks through sCtr ----
#pragma unroll 1
    for (int cc2 = 0; cc2 < 4; cc2++) {
        if (cc2) __syncthreads();
#pragma unroll
        for (int i = 0; i < 4; i++) {
            int q = tid + 256 * i;
            int k = q >> 4, jf = q & 15;
            *(float4*)(sCtr + k * 64 + jf * 4) =
                *(const float4*)(cf + (size_t)(b * NC_ + k) * C_ + cc2 * 64 + jf * 4);
        }
        __syncthreads();   // staging done; sE visible on first pass

        ull a2[4][4];
#pragma unroll
        for (int p = 0; p < 4; p++) { a2[p][0]=0; a2[p][1]=0; a2[p][2]=0; a2[p][3]=0; }

#pragma unroll 2
        for (int k4 = 0; k4 < 16; k4++) {
            ulonglong2 c0[4], c1[4];
#pragma unroll
            for (int j = 0; j < 4; j++) {
                const float* crow = sCtr + (size_t)(k4 * 4 + j) * 64;
                c0[j] = *(const ulonglong2*)(crow + kg * 4);
                c1[j] = *(const ulonglong2*)(crow + 32 + kg * 4);
            }
#pragma unroll
            for (int p = 0; p < 4; p++) {
                float4 ev = *(const float4*)(sE + (pt_g + 32 * p) * SE_STRIDE + k4 * 4);
                ull ex = pack2(ev.x, ev.x);
                fma2(a2[p][0], c0[0].x, ex); fma2(a2[p][1], c0[0].y, ex);
                fma2(a2[p][2], c1[0].x, ex); fma2(a2[p][3], c1[0].y, ex);
                ull ey = pack2(ev.y, ev.y);
                fma2(a2[p][0], c0[1].x, ey); fma2(a2[p][1], c0[1].y, ey);
                fma2(a2[p][2], c1[1].x, ey); fma2(a2[p][3], c1[1].y, ey);
                ull ez = pack2(ev.z, ev.z);
                fma2(a2[p][0], c0[2].x, ez); fma2(a2[p][1], c0[2].y, ez);
                fma2(a2[p][2], c1[2].x, ez); fma2(a2[p][3], c1[2].y, ez);
                ull ew = pack2(ev.w, ev.w);
                fma2(a2[p][0], c0[3].x, ew); fma2(a2[p][1], c0[3].y, ew);
                fma2(a2[p][2], c1[3].x, ew); fma2(a2[p][3], c1[3].y, ew);
            }
        }

        // epilogue: residual + coalesced store
#pragma unroll
        for (int p = 0; p < 4; p++) {
            size_t roff = (size_t)(pt_g + 32 * p) * C_ + cc2 * 64 + kg * 4;
            float4 v0 = *(const float4*)(pbase + roff);
            float4 v1 = *(const float4*)(pbase + roff + 32);
            float a, bb;
            unpack2(a2[p][0], a, bb); v0.x += a; v0.y += bb;
            unpack2(a2[p][1], a, bb); v0.z += a; v0.w += bb;
            unpack2(a2[p][2], a, bb); v1.x += a; v1.y += bb;
            unpack2(a2[p][3], a, bb); v1.z += a; v1.w += bb;
            *(float4*)(obase + roff)      = v0;
            *(float4*)(obase + roff + 32) = v1;
        }
    }
}

// ---------------------------------------------------------------------------
extern "C" void kernel_launch(void* const* d_in, const int* in_sizes, int n_in,
                              void* d_out, int out_size) {
    const float* pf = (const float*)d_in[0];   // point_features   (B,N,C)
    const float* cf = (const float*)d_in[1];   // centroid_features(B,NC,C)
    const float* Wp = (const float*)d_in[2];   // (C,C)
    const float* bp = (const float*)d_in[3];   // (C,)
    const float* Wc = (const float*)d_in[4];   // (C,C)
    const float* bc = (const float*)d_in[5];   // (C,)
    float* out = (float*)d_out;

    const int smem_bytes = 16384 * sizeof(float);   // 64 KB

    static bool attr_set = false;
    if (!attr_set) {
        cudaFuncSetAttribute(attn_main_kernel,
                             cudaFuncAttributeMaxDynamicSharedMemorySize,
                             smem_bytes);
        attr_set = true;
    }

    prep_kernel<<<B_ * 16, 256>>>(cf, Wp, Wc, bp, bc);
    attn_main_kernel<<<B_ * (N_ / TP_), 256, smem_bytes>>>(pf, cf, out);
}

// round 10
// speedup vs baseline: 1.1712x; 1.0143x over previous
#include <cuda_runtime.h>

#define B_   8
#define N_   16384
#define NC_  64
#define C_   256
#define TP_  128
#define SP_STRIDE 20     // P stage row stride (16 ch + 4 pad) -> conflict-free reads
#define SE_STRIDE 68     // E row stride; conflict-free octet reads

// Scratch (device globals — no allocation allowed)
__device__ float g_M[B_ * C_ * NC_];  // [b][c][k]
__device__ float g_t[B_ * NC_];       // [b][k]

typedef unsigned long long ull;

__device__ __forceinline__ ull pack2(float x, float y) {
    ull r; asm("mov.b64 %0, {%1, %2};" : "=l"(r) : "f"(x), "f"(y)); return r;
}
__device__ __forceinline__ void unpack2(ull v, float &x, float &y) {
    asm("mov.b64 {%0, %1}, %2;" : "=f"(x), "=f"(y) : "l"(v));
}
__device__ __forceinline__ void fma2(ull &acc, ull a, ull b) {
    asm("fma.rn.f32x2 %0, %1, %2, %3;" : "=l"(acc) : "l"(a), "l"(b), "l"(acc));
}
__device__ __forceinline__ float warp_sum(float s) {
#pragma unroll
    for (int off = 16; off; off >>= 1) s += __shfl_xor_sync(0xffffffffu, s, off);
    return s;
}

// ---------------------------------------------------------------------------
// Prep kernel (unchanged). grid 128 = (b<<4 | kt), block 256.
// ---------------------------------------------------------------------------
__global__ void prep_kernel(const float* __restrict__ cf, const float* __restrict__ Wp,
                            const float* __restrict__ Wc, const float* __restrict__ bp,
                            const float* __restrict__ bc) {
    __shared__ __align__(16) float sCt[C_ * 4];
    __shared__ __align__(16) float sCPt[C_ * 4];
    __shared__ __align__(16) float sTile[8448];
    __shared__ float sPart[8][4];

    int b  = blockIdx.x >> 4;
    int kt = blockIdx.x & 15;
    int tid = threadIdx.x, w = tid >> 5, l = tid & 31;

#pragma unroll
    for (int i = 0; i < 4; i++)
        sCt[tid * 4 + i] = cf[(size_t)(b * NC_ + kt * 4 + i) * C_ + tid];
    __syncthreads();

    int d = tid;
    float acc[4];
    {
        float bcv = bc[d];
#pragma unroll
        for (int j = 0; j < 4; j++) acc[j] = bcv;
    }
    const float4* Wc4 = (const float4*)Wc;
    for (int e0 = 0; e0 < C_; e0 += 32) {
#pragma unroll
        for (int i = 0; i < 8; i++) {
            int q = tid + 256 * i;
            int ee = q >> 6, jf = q & 63;
            ((float4*)sTile)[ee * 66 + jf] = Wc4[(size_t)(e0 + ee) * 64 + jf];
        }
        __syncthreads();
#pragma unroll 4
        for (int ee = 0; ee < 32; ee++) {
            float wv = sTile[ee * 264 + d];
            float4 c0 = *(const float4*)(sCt + (e0 + ee) * 4);
            acc[0] += wv*c0.x; acc[1] += wv*c0.y; acc[2] += wv*c0.z; acc[3] += wv*c0.w;
        }
        __syncthreads();
    }
    {
        float m = bp[d];
#pragma unroll
        for (int j = 0; j < 4; j++) {
            float s = warp_sum(acc[j] * m);
            if (l == 0) sPart[w][j] = s;
        }
    }
    *(float4*)(sCPt + d * 4) = make_float4(acc[0], acc[1], acc[2], acc[3]);
    __syncthreads();
    if (tid < 4) {
        float s = 0.f;
#pragma unroll
        for (int ww = 0; ww < 8; ww++) s += sPart[ww][tid];
        g_t[b * NC_ + kt * 4 + tid] = s;
    }

    int c = tid;
    float a2[4] = {0.f, 0.f, 0.f, 0.f};
    const float4* Wp4 = (const float4*)Wp;
    for (int d0 = 0; d0 < C_; d0 += 32) {
        __syncthreads();
#pragma unroll
        for (int i = 0; i < 8; i++) {
            int q = tid + 256 * i;
            int cc = q >> 3, jf = q & 7;
            float4 v = Wp4[(size_t)cc * 64 + d0 / 4 + jf];
            float* dst = sTile + cc * 33 + jf * 4;
            dst[0] = v.x; dst[1] = v.y; dst[2] = v.z; dst[3] = v.w;
        }
        __syncthreads();
#pragma unroll 4
        for (int dd = 0; dd < 32; dd++) {
            float wv = sTile[c * 33 + dd];
            float4 q0 = *(const float4*)(sCPt + (d0 + dd) * 4);
            a2[0] += wv*q0.x; a2[1] += wv*q0.y; a2[2] += wv*q0.z; a2[3] += wv*q0.w;
        }
    }
#pragma unroll
    for (int j = 0; j < 4; j++)
        g_M[(size_t)(b * C_ + c) * NC_ + kt * 4 + j] = a2[j];
}

// ---------------------------------------------------------------------------
// Main kernel. Block 256 thr, 128 points, 3 blocks/SM.
// Tile: 4 pts (pt_g+32p) x 8 k/ch (kg octet {kg*4..+3} U {32+kg*4..+3}).
// Phase 1: P staged via smem in 16-ch chunks (coalesced LDG -> conflict-free LDS).
// Phase 2: E via smem, Ctr staged per 64-ch chunk.
// dyn smem = 18944 floats (75.8 KB):
//   phase1: sM [0,16384) M[c][64];  sP [16384, 16384+128*20)
//   phase2 overlay: sE [0, 128*68), sCtr [8704, 8704+4096)
// ---------------------------------------------------------------------------
__global__ __launch_bounds__(256, 3)
void attn_main_kernel(const float* __restrict__ pf, const float* __restrict__ cf,
                      float* __restrict__ out) {
    extern __shared__ __align__(16) float sm[];
    float* sM   = sm;
    float* sP   = sm + 16384;
    float* sE   = sm;
    float* sCtr = sm + 8704;
    __shared__ __align__(16) float st[NC_];

    int b    = blockIdx.x >> 7;
    int tile = blockIdx.x & 127;
    int tid  = threadIdx.x;
    int pt_g = tid >> 3;   // 0..31
    int kg   = tid & 7;

    {
        const float4* Ms = (const float4*)(g_M + (size_t)b * C_ * NC_);
        float4* s4 = (float4*)sM;
#pragma unroll
        for (int i = 0; i < 16; i++) s4[tid + 256 * i] = Ms[tid + 256 * i];
        if (tid < NC_) st[tid] = g_t[b * NC_ + tid];
    }
    __syncthreads();

    size_t ptbase = (size_t)b * N_ + (size_t)tile * TP_;
    const float* pbase = pf + ptbase * C_;
    float* obase = out + ptbase * C_;

    // ---- phase 1: scores ----
    ull acc[4][4];
    {
        const ull* t2 = (const ull*)st;
        ull i0 = t2[2*kg], i1 = t2[2*kg+1], i2 = t2[16+2*kg], i3 = t2[17+2*kg];
#pragma unroll
        for (int p = 0; p < 4; p++) {
            acc[p][0] = i0; acc[p][1] = i1; acc[p][2] = i2; acc[p][3] = i3;
        }
    }

#pragma unroll 1
    for (int ch = 0; ch < 16; ch++) {      // 16-channel chunks
        if (ch) __syncthreads();
        // stage P[128 pts][16 ch]: 512 float4, 2 per thread, coalesced LDG
#pragma unroll
        for (int i = 0; i < 2; i++) {
            int q  = tid + 256 * i;
            int pt = q >> 2, jf = q & 3;
            *(float4*)(sP + pt * SP_STRIDE + jf * 4) =
                *(const float4*)(pbase + (size_t)pt * C_ + ch * 16 + jf * 4);
        }
        __syncthreads();

#pragma unroll
        for (int c4 = 0; c4 < 4; c4++) {
            ulonglong2 m0[4], m1[4];
#pragma unroll
            for (int j = 0; j < 4; j++) {
                const float* mrow = sM + (size_t)(ch * 16 + c4 * 4 + j) * NC_;
                m0[j] = *(const ulonglong2*)(mrow + kg * 4);
                m1[j] = *(const ulonglong2*)(mrow + 32 + kg * 4);
            }
#pragma unroll
            for (int p = 0; p < 4; p++) {
                float4 pv = *(const float4*)(sP + (pt_g + 32 * p) * SP_STRIDE + c4 * 4);
                ull px = pack2(pv.x, pv.x);
                fma2(acc[p][0], m0[0].x, px); fma2(acc[p][1], m0[0].y, px);
                fma2(acc[p][2], m1[0].x, px); fma2(acc[p][3], m1[0].y, px);
                ull py = pack2(pv.y, pv.y);
                fma2(acc[p][0], m0[1].x, py); fma2(acc[p][1], m0[1].y, py);
                fma2(acc[p][2], m1[1].x, py); fma2(acc[p][3], m1[1].y, py);
                ull pz = pack2(pv.z, pv.z);
                fma2(acc[p][0], m0[2].x, pz); fma2(acc[p][1], m0[2].y, pz);
                fma2(acc[p][2], m1[2].x, pz); fma2(acc[p][3], m1[2].y, pz);
                ull pw = pack2(pv.w, pv.w);
                fma2(acc[p][0], m0[3].x, pw); fma2(acc[p][1], m0[3].y, pw);
                fma2(acc[p][2], m1[3].x, pw); fma2(acc[p][3], m1[3].y, pw);
            }
        }
    }

    // ---- softmax per point (8 kg lanes hold the 64 k) ----
#pragma unroll
    for (int p = 0; p < 4; p++) {
        float x0,x1,x2,x3,x4,x5,x6,x7;
        unpack2(acc[p][0], x0, x1); unpack2(acc[p][1], x2, x3);
        unpack2(acc[p][2], x4, x5); unpack2(acc[p][3], x6, x7);
        float mx = fmaxf(fmaxf(fmaxf(x0,x1),fmaxf(x2,x3)), fmaxf(fmaxf(x4,x5),fmaxf(x6,x7)));
#pragma unroll
        for (int off = 1; off < 8; off <<= 1)
            mx = fmaxf(mx, __shfl_xor_sync(0xffffffffu, mx, off));
        x0 = __expf(x0-mx); x1 = __expf(x1-mx); x2 = __expf(x2-mx); x3 = __expf(x3-mx);
        x4 = __expf(x4-mx); x5 = __expf(x5-mx); x6 = __expf(x6-mx); x7 = __expf(x7-mx);
        float s = ((x0+x1)+(x2+x3)) + ((x4+x5)+(x6+x7));
#pragma unroll
        for (int off = 1; off < 8; off <<= 1)
            s += __shfl_xor_sync(0xffffffffu, s, off);
        float inv = 1.0f / s;
        acc[p][0] = pack2(x0*inv, x1*inv); acc[p][1] = pack2(x2*inv, x3*inv);
        acc[p][2] = pack2(x4*inv, x5*inv); acc[p][3] = pack2(x6*inv, x7*inv);
    }

    __syncthreads();   // all phase-1 sM/sP reads complete (sE/sCtr overlay)

    // ---- stage E: sE[pt][64] ----
#pragma unroll
    for (int p = 0; p < 4; p++) {
        float* er = sE + (pt_g + 32 * p) * SE_STRIDE;
        ulonglong2 e0; e0.x = acc[p][0]; e0.y = acc[p][1];
        ulonglong2 e1; e1.x = acc[p][2]; e1.y = acc[p][3];
        *(ulonglong2*)(er + kg * 4)      = e0;
        *(ulonglong2*)(er + 32 + kg * 4) = e1;
    }

    // ---- phase 2: stream Ctr 64-ch chunks through sCtr ----
#pragma unroll 1
    for (int cc2 = 0; cc2 < 4; cc2++) {
        if (cc2) __syncthreads();
#pragma unroll
        for (int i = 0; i < 4; i++) {
            int q = tid + 256 * i;
            int k = q >> 4, jf = q & 15;
            *(float4*)(sCtr + k * 64 + jf * 4) =
                *(const float4*)(cf + (size_t)(b * NC_ + k) * C_ + cc2 * 64 + jf * 4);
        }
        __syncthreads();   // staging done; sE visible on first pass

        ull a2[4][4];
#pragma unroll
        for (int p = 0; p < 4; p++) { a2[p][0]=0; a2[p][1]=0; a2[p][2]=0; a2[p][3]=0; }

#pragma unroll 2
        for (int k4 = 0; k4 < 16; k4++) {
            ulonglong2 c0[4], c1[4];
#pragma unroll
            for (int j = 0; j < 4; j++) {
                const float* crow = sCtr + (size_t)(k4 * 4 + j) * 64;
                c0[j] = *(const ulonglong2*)(crow + kg * 4);
                c1[j] = *(const ulonglong2*)(crow + 32 + kg * 4);
            }
#pragma unroll
            for (int p = 0; p < 4; p++) {
                float4 ev = *(const float4*)(sE + (pt_g + 32 * p) * SE_STRIDE + k4 * 4);
                ull ex = pack2(ev.x, ev.x);
                fma2(a2[p][0], c0[0].x, ex); fma2(a2[p][1], c0[0].y, ex);
                fma2(a2[p][2], c1[0].x, ex); fma2(a2[p][3], c1[0].y, ex);
                ull ey = pack2(ev.y, ev.y);
                fma2(a2[p][0], c0[1].x, ey); fma2(a2[p][1], c0[1].y, ey);
                fma2(a2[p][2], c1[1].x, ey); fma2(a2[p][3], c1[1].y, ey);
                ull ez = pack2(ev.z, ev.z);
                fma2(a2[p][0], c0[2].x, ez); fma2(a2[p][1], c0[2].y, ez);
                fma2(a2[p][2], c1[2].x, ez); fma2(a2[p][3], c1[2].y, ez);
                ull ew = pack2(ev.w, ev.w);
                fma2(a2[p][0], c0[3].x, ew); fma2(a2[p][1], c0[3].y, ew);
                fma2(a2[p][2], c1[3].x, ew); fma2(a2[p][3], c1[3].y, ew);
            }
        }

        // epilogue: residual + coalesced store
#pragma unroll
        for (int p = 0; p < 4; p++) {
            size_t roff = (size_t)(pt_g + 32 * p) * C_ + cc2 * 64 + kg * 4;
            float4 v0 = *(const float4*)(pbase + roff);
            float4 v1 = *(const float4*)(pbase + roff + 32);
            float a, bb;
            unpack2(a2[p][0], a, bb); v0.x += a; v0.y += bb;
            unpack2(a2[p][1], a, bb); v0.z += a; v0.w += bb;
            unpack2(a2[p][2], a, bb); v1.x += a; v1.y += bb;
            unpack2(a2[p][3], a, bb); v1.z += a; v1.w += bb;
            *(float4*)(obase + roff)      = v0;
            *(float4*)(obase + roff + 32) = v1;
        }
    }
}

// ---------------------------------------------------------------------------
extern "C" void kernel_launch(void* const* d_in, const int* in_sizes, int n_in,
                              void* d_out, int out_size) {
    const float* pf = (const float*)d_in[0];   // point_features   (B,N,C)
    const float* cf = (const float*)d_in[1];   // centroid_features(B,NC,C)
    const float* Wp = (const float*)d_in[2];   // (C,C)
    const float* bp = (const float*)d_in[3];   // (C,)
    const float* Wc = (const float*)d_in[4];   // (C,C)
    const float* bc = (const float*)d_in[5];   // (C,)
    float* out = (float*)d_out;

    const int smem_bytes = 18944 * sizeof(float);   // 75.8 KB -> 3 blocks/SM

    static bool attr_set = false;
    if (!attr_set) {
        cudaFuncSetAttribute(attn_main_kernel,
                             cudaFuncAttributeMaxDynamicSharedMemorySize,
                             smem_bytes);
        attr_set = true;
    }

    prep_kernel<<<B_ * 16, 256>>>(cf, Wp, Wc, bp, bc);
    attn_main_kernel<<<B_ * (N_ / TP_), 256, smem_bytes>>>(pf, cf, out);
}